// round 2
// baseline (speedup 1.0000x reference)
#include <cuda_runtime.h>
#include <cuda_bf16.h>
#include <cstdint>

#define TOKENS   16384
#define HIDDEN   4096
#define EXPERTS  64

#define M_TILE   128
#define KC       64
#define NITER    (HIDDEN / KC)     // 64
#define NTHREADS 256

// ---- shared memory layout (bytes from dynamic smem base) ----
#define SM_SCALES 64
#define A_TILE_BYTES (M_TILE * 128)          // 16384 (128 rows x 128B = 64 bf16)
#define B_TILE_BYTES (EXPERTS * 128)         // 8192
#define SM_AHI    1024
#define SM_ALO    (SM_AHI + 2 * A_TILE_BYTES)   // 33792
#define SM_B      (SM_ALO + 2 * A_TILE_BYTES)   // 66560
#define SM_TOTAL  (SM_B + 2 * B_TILE_BYTES)     // 82944

// SW128 swizzle (Swizzle<3,4,3>)
#define SW(o) ((o) ^ (((o) >> 3) & 0x70))

// dequantized weights: int8 values are EXACT in bf16; scale folded into epilogue
__device__ __nv_bfloat16 g_wb[EXPERTS * HIDDEN];

// ---------------- helpers ----------------
__device__ __forceinline__ uint32_t smem_to_u32(const void* p) {
    uint32_t a;
    asm("{ .reg .u64 t; cvta.to.shared.u64 t, %1; cvt.u32.u64 %0, t; }" : "=r"(a) : "l"(p));
    return a;
}

__device__ __forceinline__ void sts128(uint32_t addr, uint32_t a, uint32_t b,
                                       uint32_t c, uint32_t d) {
    asm volatile("st.shared.v4.b32 [%0], {%1,%2,%3,%4};"
                 :: "r"(addr), "r"(a), "r"(b), "r"(c), "r"(d) : "memory");
}

// pack_bf16(lo, hi): low half-word = bf16(lo), high = bf16(hi)
__device__ __forceinline__ uint32_t pack_bf16(float lo, float hi) {
    uint32_t r;
    asm("cvt.rn.bf16x2.f32 %0, %1, %2;" : "=r"(r) : "f"(hi), "f"(lo));
    return r;
}
__device__ __forceinline__ float bf_lo(uint32_t p) { return __uint_as_float(p << 16); }
__device__ __forceinline__ float bf_hi(uint32_t p) { return __uint_as_float(p & 0xffff0000u); }

__device__ __forceinline__ void ldsm4(uint32_t (&r)[4], uint32_t addr) {
    asm volatile("ldmatrix.sync.aligned.m8n8.x4.shared.b16 {%0,%1,%2,%3}, [%4];"
                 : "=r"(r[0]), "=r"(r[1]), "=r"(r[2]), "=r"(r[3]) : "r"(addr));
}

__device__ __forceinline__ void mma16816(float (&d)[4], const uint32_t (&a)[4],
                                         uint32_t b0, uint32_t b1) {
    asm volatile("mma.sync.aligned.m16n8k16.row.col.f32.bf16.bf16.f32 "
                 "{%0,%1,%2,%3}, {%4,%5,%6,%7}, {%8,%9}, {%0,%1,%2,%3};"
                 : "+f"(d[0]), "+f"(d[1]), "+f"(d[2]), "+f"(d[3])
                 : "r"(a[0]), "r"(a[1]), "r"(a[2]), "r"(a[3]), "r"(b0), "r"(b1));
}

// ---------------- kernels ----------------

__global__ void dequant_kernel(const int* __restrict__ w) {
    int t = blockIdx.x * blockDim.x + threadIdx.x;        // 0..65535
    int4 v = ((const int4*)w)[t];
    __nv_bfloat162 p0 = __floats2bfloat162_rn((float)v.x, (float)v.y);
    __nv_bfloat162 p1 = __floats2bfloat162_rn((float)v.z, (float)v.w);
    ((__nv_bfloat162*)g_wb)[2 * t]     = p0;
    ((__nv_bfloat162*)g_wb)[2 * t + 1] = p1;
}

__global__ void __launch_bounds__(NTHREADS, 1)
gemm_kernel(const float* __restrict__ x,
            const float* __restrict__ scales,
            float* __restrict__ out) {
    extern __shared__ char smem[];
    const uint32_t sbase = smem_to_u32(smem);
    const int tid = threadIdx.x;
    const int wid = tid >> 5;
    const int lid = tid & 31;
    const int m0  = blockIdx.x * M_TILE;

    if (tid < EXPERTS) ((float*)(smem + SM_SCALES))[tid] = scales[tid];
    __syncthreads();

    // ---- producer mapping: thread -> (rows r0 & r0+64 of A tile / expert r0 of B,
    //                                   16-element quarter q of the 64-wide chunk)
    const int r0 = tid >> 2;   // 0..63
    const int q  = tid & 3;    // 0..3
    const float* xp0 = x + (size_t)(m0 + r0) * HIDDEN + q * 16;
    const float* xp1 = xp0 + (size_t)64 * HIDDEN;
    const __nv_bfloat16* wp = g_wb + (size_t)r0 * HIDDEN + q * 16;

    const uint32_t oA0 = (uint32_t)r0 * 128 + q * 32;   // byte offset within tile
    const uint32_t oA1 = oA0 + 64 * 128;

    // ---- consumer mapping (per warp): rows 16*wid .. 16*wid+15, all 64 experts
    // A ldmatrix.x4 lane address: m0=(r0-7,k0-7) m1=(r8-15,k0-7) m2=(r0-7,k8-15) m3=(r8-15,k8-15)
    const uint32_t aOff = (uint32_t)(16 * wid + (lid & 15)) * 128 + (uint32_t)(lid >> 4) * 16;
    // B ldmatrix.x4 lane address: m0=(e0-7,k0-7) m1=(e0-7,k8-15) m2=(e8-15,k0-7) m3=(e8-15,k8-15)
    const uint32_t bOff = (uint32_t)((lid & 7) + ((lid >> 4) << 3)) * 128
                        + (uint32_t)((lid >> 3) & 1) * 16;

    float acc[8][4];
#pragma unroll
    for (int n = 0; n < 8; n++)
#pragma unroll
        for (int j = 0; j < 4; j++) acc[n][j] = 0.0f;

    // prefetch chunk 0
    float4 an[8]; uint4 bn[2];
    {
        const float4* p0 = (const float4*)xp0;
        const float4* p1 = (const float4*)xp1;
        an[0] = p0[0]; an[1] = p0[1]; an[2] = p0[2]; an[3] = p0[3];
        an[4] = p1[0]; an[5] = p1[1]; an[6] = p1[2]; an[7] = p1[3];
        const uint4* pb = (const uint4*)wp;
        bn[0] = pb[0]; bn[1] = pb[1];
    }

#pragma unroll 1
    for (int i = 0; i < NITER; i++) {
        const int b = i & 1;
        const uint32_t hiB = sbase + SM_AHI + b * A_TILE_BYTES;
        const uint32_t loB = sbase + SM_ALO + b * A_TILE_BYTES;
        const uint32_t bB  = sbase + SM_B   + b * B_TILE_BYTES;

        // ---- convert chunk i (in registers) to hi/lo bf16 and store to SMEM
#pragma unroll
        for (int h = 0; h < 2; h++) {
            uint32_t hh[8], ll[8];
#pragma unroll
            for (int j = 0; j < 4; j++) {
                float4 f = an[h * 4 + j];
                uint32_t h0 = pack_bf16(f.x, f.y);
                uint32_t h1 = pack_bf16(f.z, f.w);
                float lx = f.x - bf_lo(h0);
                float ly = f.y - bf_hi(h0);
                float lz = f.z - bf_lo(h1);
                float lw = f.w - bf_hi(h1);
                hh[2 * j] = h0; hh[2 * j + 1] = h1;
                ll[2 * j] = pack_bf16(lx, ly);
                ll[2 * j + 1] = pack_bf16(lz, lw);
            }
            uint32_t o = h ? oA1 : oA0;
            sts128(hiB + SW(o),      hh[0], hh[1], hh[2], hh[3]);
            sts128(hiB + SW(o + 16), hh[4], hh[5], hh[6], hh[7]);
            sts128(loB + SW(o),      ll[0], ll[1], ll[2], ll[3]);
            sts128(loB + SW(o + 16), ll[4], ll[5], ll[6], ll[7]);
        }
        sts128(bB + SW(oA0),      bn[0].x, bn[0].y, bn[0].z, bn[0].w);
        sts128(bB + SW(oA0 + 16), bn[1].x, bn[1].y, bn[1].z, bn[1].w);

        // ---- prefetch chunk i+1 into registers (in flight across the MMA phase)
        if (i + 1 < NITER) {
            const float4* p0 = (const float4*)(xp0 + (i + 1) * KC);
            const float4* p1 = (const float4*)(xp1 + (i + 1) * KC);
            an[0] = p0[0]; an[1] = p0[1]; an[2] = p0[2]; an[3] = p0[3];
            an[4] = p1[0]; an[5] = p1[1]; an[6] = p1[2]; an[7] = p1[3];
            const uint4* pb = (const uint4*)(wp + (i + 1) * KC);
            bn[0] = pb[0]; bn[1] = pb[1];
        }

        __syncthreads();   // buffer b full; buffer b^1 reads (iter i-1) all precede this

        // ---- consume buffer b: 4 k-steps of 16, 8 n-tiles, hi+lo
#pragma unroll
        for (int ks = 0; ks < 4; ks++) {
            uint32_t ah[4], al[4];
            ldsm4(ah, hiB + SW(aOff + ks * 32));
            ldsm4(al, loB + SW(aOff + ks * 32));
#pragma unroll
            for (int np = 0; np < 4; np++) {
                uint32_t bb[4];
                ldsm4(bb, bB + SW(bOff + np * 16 * 128 + ks * 32));
                mma16816(acc[2 * np],     ah, bb[0], bb[1]);
                mma16816(acc[2 * np + 1], ah, bb[2], bb[3]);
                mma16816(acc[2 * np],     al, bb[0], bb[1]);
                mma16816(acc[2 * np + 1], al, bb[2], bb[3]);
            }
        }
    }

    // ---- epilogue: apply per-expert scales, write fp32
    const float* sc = (const float*)(smem + SM_SCALES);
    const int rbase = m0 + 16 * wid + (lid >> 2);
    const int cq = 2 * (lid & 3);
#pragma unroll
    for (int nt = 0; nt < 8; nt++) {
        const int c0 = 8 * nt + cq;
        const float s0 = sc[c0], s1 = sc[c0 + 1];
        float2 v0 = make_float2(acc[nt][0] * s0, acc[nt][1] * s1);
        float2 v1 = make_float2(acc[nt][2] * s0, acc[nt][3] * s1);
        *(float2*)(out + (size_t)rbase * EXPERTS + c0)       = v0;
        *(float2*)(out + (size_t)(rbase + 8) * EXPERTS + c0) = v1;
    }
}

extern "C" void kernel_launch(void* const* d_in, const int* in_sizes, int n_in,
                              void* d_out, int out_size) {
    const float* x      = (const float*)d_in[0];
    const int*   w      = (const int*)d_in[1];
    const float* scales = (const float*)d_in[2];
    float* out = (float*)d_out;

    cudaFuncSetAttribute(gemm_kernel, cudaFuncAttributeMaxDynamicSharedMemorySize, SM_TOTAL);

    dequant_kernel<<<256, 256>>>(w);                                  // 64*4096 int32 -> bf16
    gemm_kernel<<<TOKENS / M_TILE, NTHREADS, SM_TOTAL>>>(x, scales, out);
}